// round 4
// baseline (speedup 1.0000x reference)
#include <cuda_runtime.h>
#include <cuda_bf16.h>
#include <math.h>
#include <stdint.h>

// Problem constants
#define BATCH 2
#define SEQ   2048
#define DMODEL 2048
#define NHEADS 16
#define NKV 4
#define HDIM 128
#define GRP (NHEADS / NKV)          // 4
#define MTOT (BATCH * SEQ)          // 4096
#define QDIM (NHEADS * HDIM)        // 2048
#define KVDIM (NKV * HDIM)          // 512

// ---------------------------------------------------------------------------
// Packed fp32x2 helpers (Blackwell f32x2 pipe — FFMA2 in SASS).
// Each lane is a full IEEE fp32 op; precision identical to scalar fmaf.
// ---------------------------------------------------------------------------
__device__ __forceinline__ uint64_t ffma2(uint64_t a, uint64_t b, uint64_t c) {
    uint64_t d;
    asm("fma.rn.f32x2 %0, %1, %2, %3;" : "=l"(d) : "l"(a), "l"(b), "l"(c));
    return d;
}
__device__ __forceinline__ uint64_t fmul2(uint64_t a, uint64_t b) {
    uint64_t d;
    asm("mul.rn.f32x2 %0, %1, %2;" : "=l"(d) : "l"(a), "l"(b));
    return d;
}
__device__ __forceinline__ uint64_t pack2(float x, float y) {
    uint64_t d;
    asm("mov.b64 %0, {%1, %2};" : "=l"(d) : "f"(x), "f"(y));
    return d;
}
__device__ __forceinline__ float2 unpack2(uint64_t v) {
    float2 r;
    asm("mov.b64 {%0, %1}, %2;" : "=f"(r.x), "=f"(r.y) : "l"(v));
    return r;
}

// ---------------------------------------------------------------------------
// Scratch (device globals — no allocation allowed)
// ---------------------------------------------------------------------------
__device__ float g_Q[MTOT * QDIM];   // [B,S,H,D]
__device__ float g_K[MTOT * KVDIM];  // [B,S,Hk,D]
__device__ float g_V[MTOT * KVDIM];  // [B,S,Hk,D]
__device__ float g_O[MTOT * QDIM];   // [B,S,H,D]

// ---------------------------------------------------------------------------
// SGEMM: C[M,N] = A[M,K] @ B[K,N] + bias[N]
// BM=BN=128, BK=8, 256 threads, 8x8 per thread, accumulators packed in f32x2
// across column pairs. Double-buffered smem, one barrier per K-step.
// ---------------------------------------------------------------------------
__global__ __launch_bounds__(256, 2)
void sgemm_bias_kernel(const float* __restrict__ A,
                       const float* __restrict__ B,
                       const float* __restrict__ bias,
                       float* __restrict__ C,
                       int M, int N, int K)
{
    __shared__ float As[2][8][128];
    __shared__ float Bs[2][8][128];

    const int t  = threadIdx.x;
    const int m0 = blockIdx.y * 128;
    const int n0 = blockIdx.x * 128;

    const int aRow  = t >> 1;          // 0..127
    const int aQuad = (t & 1) * 4;     // 0 or 4
    const int bRow = t >> 5;           // 0..7
    const int bCol = (t & 31) * 4;     // 0..124

    const int ty = t >> 4;             // 0..15
    const int tx = t & 15;             // 0..15
    const int r0 = ty * 4;
    const int c0 = tx * 4;

    uint64_t acc2[8][4];
#pragma unroll
    for (int i = 0; i < 8; i++)
#pragma unroll
        for (int j = 0; j < 4; j++) acc2[i][j] = 0ull;

    const float* Aptr = A + (size_t)(m0 + aRow) * K + aQuad;
    const float* Bptr = B + (size_t)bRow * N + n0 + bCol;

    {
        float4 av = *(const float4*)(Aptr);
        As[0][aQuad + 0][aRow] = av.x;
        As[0][aQuad + 1][aRow] = av.y;
        As[0][aQuad + 2][aRow] = av.z;
        As[0][aQuad + 3][aRow] = av.w;
        *(float4*)(&Bs[0][bRow][bCol]) = *(const float4*)(Bptr);
    }
    __syncthreads();

    int cur = 0;
    for (int k0 = 0; k0 < K; k0 += 8) {
        const int next = cur ^ 1;
        const bool more = (k0 + 8) < K;

        float4 avn, bvn;
        if (more) {
            avn = *(const float4*)(Aptr + k0 + 8);
            bvn = *(const float4*)(Bptr + (size_t)(k0 + 8) * N);
        }

#pragma unroll
        for (int k = 0; k < 8; k++) {
            float4 a0 = *(const float4*)(&As[cur][k][r0]);
            float4 a1 = *(const float4*)(&As[cur][k][64 + r0]);
            ulonglong2 bd0 = *(const ulonglong2*)(&Bs[cur][k][c0]);
            ulonglong2 bd1 = *(const ulonglong2*)(&Bs[cur][k][64 + c0]);
            float am[8] = {a0.x, a0.y, a0.z, a0.w, a1.x, a1.y, a1.z, a1.w};
#pragma unroll
            for (int i = 0; i < 8; i++) {
                uint64_t am2 = pack2(am[i], am[i]);
                acc2[i][0] = ffma2(am2, bd0.x, acc2[i][0]);
                acc2[i][1] = ffma2(am2, bd0.y, acc2[i][1]);
                acc2[i][2] = ffma2(am2, bd1.x, acc2[i][2]);
                acc2[i][3] = ffma2(am2, bd1.y, acc2[i][3]);
            }
        }

        if (more) {
            As[next][aQuad + 0][aRow] = avn.x;
            As[next][aQuad + 1][aRow] = avn.y;
            As[next][aQuad + 2][aRow] = avn.z;
            As[next][aQuad + 3][aRow] = avn.w;
            *(float4*)(&Bs[next][bRow][bCol]) = bvn;
        }
        __syncthreads();
        cur = next;
    }

    float4 bb0 = *(const float4*)(bias + n0 + c0);
    float4 bb1 = *(const float4*)(bias + n0 + 64 + c0);

#pragma unroll
    for (int i = 0; i < 8; i++) {
        int row = m0 + ((i < 4) ? (r0 + i) : (64 + r0 + i - 4));
        float* Crow = C + (size_t)row * N + n0;
        float2 u0 = unpack2(acc2[i][0]);
        float2 u1 = unpack2(acc2[i][1]);
        float2 u2 = unpack2(acc2[i][2]);
        float2 u3 = unpack2(acc2[i][3]);
        float4 v0 = make_float4(u0.x + bb0.x, u0.y + bb0.y,
                                u1.x + bb0.z, u1.y + bb0.w);
        float4 v1 = make_float4(u2.x + bb1.x, u2.y + bb1.y,
                                u3.x + bb1.z, u3.y + bb1.w);
        *(float4*)(Crow + c0)      = v0;
        *(float4*)(Crow + 64 + c0) = v1;
    }
}

// ---------------------------------------------------------------------------
// Flash attention, fp32 with f32x2-packed FMAs. Br = Bc = 64, D = 128.
// grid: (SEQ/64, NHEADS, BATCH), 256 threads.
// Thread map: r = t/4 (query row), l = t%4.
//   scores:  thread owns j = 4*jj + l  (jj = 0..15)   -> lanes read stride-1
//            rows of sK: conflict-free with row pitch 132.
//   PV dims: thread owns float4 slots sl = l + 4*i2 (i2 = 0..7) -> lanes read
//            stride-4 slots of sV row: conflict-free.
// Pitches: Q/K/V rows 132 floats (16B-aligned, bank-skewed); sP rows 65.
// smem: 3*64*132 + 64*65 floats = 118016 bytes
// ---------------------------------------------------------------------------
#define ROWP 132
#define PP   65
#define ATTN_SMEM ((64 * ROWP * 3 + 64 * PP) * 4)

__global__ __launch_bounds__(256, 1)
void flash_attn_kernel(const float* __restrict__ Qg,
                       const float* __restrict__ Kg,
                       const float* __restrict__ Vg,
                       float* __restrict__ Og)
{
    extern __shared__ float smem[];
    float* sQ = smem;                     // 64*ROWP
    float* sK = smem + 64 * ROWP;         // 64*ROWP
    float* sV = smem + 2 * 64 * ROWP;     // 64*ROWP
    float* sP = smem + 3 * 64 * ROWP;     // 64*PP

    const int t  = threadIdx.x;
    const int q0 = blockIdx.x * 64;
    const int h  = blockIdx.y;
    const int b  = blockIdx.z;
    const int hk = h >> 2;            // h / GRP

    const int r = t >> 2;             // 0..63 query row within tile
    const int l = t & 3;              // 0..3

    const float scale = 0.08838834764831845f;  // 1/sqrt(128)

    // ---- load Q tile (scaled, padded pitch) ----
#pragma unroll
    for (int i = 0; i < 8; i++) {
        int idx = t + i * 256;           // 0..2047 float4 slots
        int qr  = idx >> 5;              // 0..63
        int c4  = idx & 31;              // 0..31
        const float4* src = (const float4*)(Qg +
            ((size_t)((b * SEQ + q0 + qr) * NHEADS + h)) * HDIM) + c4;
        float4 v = *src;
        v.x *= scale; v.y *= scale; v.z *= scale; v.w *= scale;
        ((float4*)(sQ + qr * ROWP))[c4] = v;
    }

    // acc2[2*i2 + p]: packed output dims of float4 slot (l + 4*i2), pair p
    uint64_t acc2[16];
#pragma unroll
    for (int i = 0; i < 16; i++) acc2[i] = 0ull;
    float row_max = -INFINITY;
    float row_sum = 0.f;

    for (int kt = 0; kt < SEQ / 64; kt++) {
        const int k0 = kt * 64;
        __syncthreads();   // protect sK/sV (prev PV reads) and sQ first iter
        // ---- load K, V tiles ----
#pragma unroll
        for (int i = 0; i < 8; i++) {
            int idx = t + i * 256;
            int kr  = idx >> 5;
            int c4  = idx & 31;
            size_t base = ((size_t)((b * SEQ + k0 + kr) * NKV + hk)) * HDIM;
            ((float4*)(sK + kr * ROWP))[c4] = ((const float4*)(Kg + base))[c4];
            ((float4*)(sV + kr * ROWP))[c4] = ((const float4*)(Vg + base))[c4];
        }
        __syncthreads();

        // ---- scores: s[jj] = Q[r] . K[4*jj + l], packed over head-dim ----
        uint64_t s2[16];
#pragma unroll
        for (int jj = 0; jj < 16; jj++) s2[jj] = 0ull;
        {
            const ulonglong2* q2p = (const ulonglong2*)(sQ + r * ROWP);
#pragma unroll 4
            for (int kk = 0; kk < 32; kk++) {       // 32 x 4 floats = 128 dims
                ulonglong2 q2 = q2p[kk];
#pragma unroll
                for (int jj = 0; jj < 16; jj++) {
                    ulonglong2 k2 =
                        ((const ulonglong2*)(sK + (4 * jj + l) * ROWP))[kk];
                    s2[jj] = ffma2(q2.x, k2.x, s2[jj]);
                    s2[jj] = ffma2(q2.y, k2.y, s2[jj]);
                }
            }
        }
        float s[16];
#pragma unroll
        for (int jj = 0; jj < 16; jj++) {
            float2 u = unpack2(s2[jj]);
            s[jj] = u.x + u.y;
        }

        // ---- streaming softmax update ----
        float tmax = s[0];
#pragma unroll
        for (int jj = 1; jj < 16; jj++) tmax = fmaxf(tmax, s[jj]);
        tmax = fmaxf(tmax, __shfl_xor_sync(0xffffffffu, tmax, 1));
        tmax = fmaxf(tmax, __shfl_xor_sync(0xffffffffu, tmax, 2));
        float m_new = fmaxf(row_max, tmax);
        float alpha = __expf(row_max - m_new);  // 0 on first tile

        float lsum = 0.f;
#pragma unroll
        for (int jj = 0; jj < 16; jj++) {
            s[jj] = __expf(s[jj] - m_new);
            lsum += s[jj];
        }
        lsum += __shfl_xor_sync(0xffffffffu, lsum, 1);
        lsum += __shfl_xor_sync(0xffffffffu, lsum, 2);
        row_sum = row_sum * alpha + lsum;
        row_max = m_new;

        uint64_t alpha2 = pack2(alpha, alpha);
#pragma unroll
        for (int i = 0; i < 16; i++) acc2[i] = fmul2(acc2[i], alpha2);

        // write P tile (thread owns columns 4*jj + l)
#pragma unroll
        for (int jj = 0; jj < 16; jj++)
            sP[r * PP + 4 * jj + l] = s[jj];
        __syncthreads();

        // ---- PV: acc += P[r,j] * V[j, slots l+4*i2] ----
        const ulonglong2* vrow = (const ulonglong2*)sV;
        for (int j = 0; j < 64; j++) {
            float p = sP[r * PP + j];
            uint64_t p2 = pack2(p, p);
            const ulonglong2* v2 = (const ulonglong2*)(sV + j * ROWP);
#pragma unroll
            for (int i2 = 0; i2 < 8; i2++) {
                ulonglong2 vv = v2[l + 4 * i2];
                acc2[2 * i2]     = ffma2(p2, vv.x, acc2[2 * i2]);
                acc2[2 * i2 + 1] = ffma2(p2, vv.y, acc2[2 * i2 + 1]);
            }
        }
        (void)vrow;
    }

    // ---- normalize + store (thread owns float4 slots l + 4*i2) ----
    float inv = 1.0f / row_sum;
    uint64_t inv2 = pack2(inv, inv);
    float4* op = (float4*)(Og +
        ((size_t)((b * SEQ + q0 + r) * NHEADS + h)) * HDIM);
#pragma unroll
    for (int i2 = 0; i2 < 8; i2++) {
        float2 ua = unpack2(fmul2(acc2[2 * i2], inv2));
        float2 ub = unpack2(fmul2(acc2[2 * i2 + 1], inv2));
        op[l + 4 * i2] = make_float4(ua.x, ua.y, ub.x, ub.y);
    }
}

// ---------------------------------------------------------------------------
// Launch
// ---------------------------------------------------------------------------
extern "C" void kernel_launch(void* const* d_in, const int* in_sizes, int n_in,
                              void* d_out, int out_size)
{
    const float* x  = (const float*)d_in[0];
    const float* wq = (const float*)d_in[1];
    const float* bq = (const float*)d_in[2];
    const float* wk = (const float*)d_in[3];
    const float* bk = (const float*)d_in[4];
    const float* wv = (const float*)d_in[5];
    const float* bv = (const float*)d_in[6];
    const float* wo = (const float*)d_in[7];
    const float* bo = (const float*)d_in[8];
    float* out = (float*)d_out;

    float *Q, *K, *V, *O;
    cudaGetSymbolAddress((void**)&Q, g_Q);
    cudaGetSymbolAddress((void**)&K, g_K);
    cudaGetSymbolAddress((void**)&V, g_V);
    cudaGetSymbolAddress((void**)&O, g_O);

    // QKV projections
    sgemm_bias_kernel<<<dim3(QDIM / 128, MTOT / 128), 256>>>(
        x, wq, bq, Q, MTOT, QDIM, DMODEL);
    sgemm_bias_kernel<<<dim3(KVDIM / 128, MTOT / 128), 256>>>(
        x, wk, bk, K, MTOT, KVDIM, DMODEL);
    sgemm_bias_kernel<<<dim3(KVDIM / 128, MTOT / 128), 256>>>(
        x, wv, bv, V, MTOT, KVDIM, DMODEL);

    // Attention
    cudaFuncSetAttribute(flash_attn_kernel,
                         cudaFuncAttributeMaxDynamicSharedMemorySize, ATTN_SMEM);
    flash_attn_kernel<<<dim3(SEQ / 64, NHEADS, BATCH), 256, ATTN_SMEM>>>(
        Q, K, V, O);

    // Output projection
    sgemm_bias_kernel<<<dim3(DMODEL / 128, MTOT / 128), 256>>>(
        O, wo, bo, out, MTOT, DMODEL, DMODEL);
}

// round 13
// speedup vs baseline: 2.3471x; 2.3471x over previous
#include <cuda_runtime.h>
#include <cuda_bf16.h>
#include <math.h>
#include <stdint.h>

// Problem constants
#define BATCH 2
#define SEQ   2048
#define DMODEL 2048
#define NHEADS 16
#define NKV 4
#define HDIM 128
#define GRP (NHEADS / NKV)          // 4
#define MTOT (BATCH * SEQ)          // 4096
#define QDIM (NHEADS * HDIM)        // 2048
#define KVDIM (NKV * HDIM)          // 512

// ---------------------------------------------------------------------------
// Packed fp32x2 helpers (FFMA2 in SASS). IEEE fp32 per lane.
// ---------------------------------------------------------------------------
__device__ __forceinline__ uint64_t ffma2(uint64_t a, uint64_t b, uint64_t c) {
    uint64_t d;
    asm("fma.rn.f32x2 %0, %1, %2, %3;" : "=l"(d) : "l"(a), "l"(b), "l"(c));
    return d;
}
__device__ __forceinline__ uint64_t fmul2(uint64_t a, uint64_t b) {
    uint64_t d;
    asm("mul.rn.f32x2 %0, %1, %2;" : "=l"(d) : "l"(a), "l"(b));
    return d;
}
__device__ __forceinline__ uint64_t pack2(float x, float y) {
    uint64_t d;
    asm("mov.b64 %0, {%1, %2};" : "=l"(d) : "f"(x), "f"(y));
    return d;
}
__device__ __forceinline__ float2 unpack2(uint64_t v) {
    float2 r;
    asm("mov.b64 {%0, %1}, %2;" : "=f"(r.x), "=f"(r.y) : "l"(v));
    return r;
}

// ---------------------------------------------------------------------------
// Scratch (device globals — no allocation allowed)
// ---------------------------------------------------------------------------
__device__ float g_Q[MTOT * QDIM];   // [B,S,H,D]
__device__ float g_K[MTOT * KVDIM];  // [B,S,Hk,D]
__device__ float g_V[MTOT * KVDIM];  // [B,S,Hk,D]
__device__ float g_O[MTOT * QDIM];   // [B,S,H,D]

// ---------------------------------------------------------------------------
// SGEMM: C[M,N] = A[M,K] @ B[K,N] + bias[N]  (proven correct in round 4)
// ---------------------------------------------------------------------------
__global__ __launch_bounds__(256, 2)
void sgemm_bias_kernel(const float* __restrict__ A,
                       const float* __restrict__ B,
                       const float* __restrict__ bias,
                       float* __restrict__ C,
                       int M, int N, int K)
{
    __shared__ float As[2][8][128];
    __shared__ float Bs[2][8][128];

    const int t  = threadIdx.x;
    const int m0 = blockIdx.y * 128;
    const int n0 = blockIdx.x * 128;

    const int aRow  = t >> 1;
    const int aQuad = (t & 1) * 4;
    const int bRow = t >> 5;
    const int bCol = (t & 31) * 4;

    const int ty = t >> 4;
    const int tx = t & 15;
    const int r0 = ty * 4;
    const int c0 = tx * 4;

    uint64_t acc2[8][4];
#pragma unroll
    for (int i = 0; i < 8; i++)
#pragma unroll
        for (int j = 0; j < 4; j++) acc2[i][j] = 0ull;

    const float* Aptr = A + (size_t)(m0 + aRow) * K + aQuad;
    const float* Bptr = B + (size_t)bRow * N + n0 + bCol;

    {
        float4 av = *(const float4*)(Aptr);
        As[0][aQuad + 0][aRow] = av.x;
        As[0][aQuad + 1][aRow] = av.y;
        As[0][aQuad + 2][aRow] = av.z;
        As[0][aQuad + 3][aRow] = av.w;
        *(float4*)(&Bs[0][bRow][bCol]) = *(const float4*)(Bptr);
    }
    __syncthreads();

    int cur = 0;
    for (int k0 = 0; k0 < K; k0 += 8) {
        const int next = cur ^ 1;
        const bool more = (k0 + 8) < K;

        float4 avn, bvn;
        if (more) {
            avn = *(const float4*)(Aptr + k0 + 8);
            bvn = *(const float4*)(Bptr + (size_t)(k0 + 8) * N);
        }

#pragma unroll
        for (int k = 0; k < 8; k++) {
            float4 a0 = *(const float4*)(&As[cur][k][r0]);
            float4 a1 = *(const float4*)(&As[cur][k][64 + r0]);
            ulonglong2 bd0 = *(const ulonglong2*)(&Bs[cur][k][c0]);
            ulonglong2 bd1 = *(const ulonglong2*)(&Bs[cur][k][64 + c0]);
            float am[8] = {a0.x, a0.y, a0.z, a0.w, a1.x, a1.y, a1.z, a1.w};
#pragma unroll
            for (int i = 0; i < 8; i++) {
                uint64_t am2 = pack2(am[i], am[i]);
                acc2[i][0] = ffma2(am2, bd0.x, acc2[i][0]);
                acc2[i][1] = ffma2(am2, bd0.y, acc2[i][1]);
                acc2[i][2] = ffma2(am2, bd1.x, acc2[i][2]);
                acc2[i][3] = ffma2(am2, bd1.y, acc2[i][3]);
            }
        }

        if (more) {
            As[next][aQuad + 0][aRow] = avn.x;
            As[next][aQuad + 1][aRow] = avn.y;
            As[next][aQuad + 2][aRow] = avn.z;
            As[next][aQuad + 3][aRow] = avn.w;
            *(float4*)(&Bs[next][bRow][bCol]) = bvn;
        }
        __syncthreads();
        cur = next;
    }

    float4 bb0 = *(const float4*)(bias + n0 + c0);
    float4 bb1 = *(const float4*)(bias + n0 + 64 + c0);

#pragma unroll
    for (int i = 0; i < 8; i++) {
        int row = m0 + ((i < 4) ? (r0 + i) : (64 + r0 + i - 4));
        float* Crow = C + (size_t)row * N + n0;
        float2 u0 = unpack2(acc2[i][0]);
        float2 u1 = unpack2(acc2[i][1]);
        float2 u2 = unpack2(acc2[i][2]);
        float2 u3 = unpack2(acc2[i][3]);
        float4 v0 = make_float4(u0.x + bb0.x, u0.y + bb0.y,
                                u1.x + bb0.z, u1.y + bb0.w);
        float4 v1 = make_float4(u2.x + bb1.x, u2.y + bb1.y,
                                u3.x + bb1.z, u3.y + bb1.w);
        *(float4*)(Crow + c0)      = v0;
        *(float4*)(Crow + 64 + c0) = v1;
    }
}

// ---------------------------------------------------------------------------
// Flash attention, register-tiled + software-pipelined K/V loads.
// Br=128, Bc=64, D=128, 256 threads.
// Thread (ty = t/16, tx = t%16):
//   score: owns q-rows 8ty..8ty+7 x k-cols 4tx..4tx+3
//   PV:    owns q-rows 8ty..8ty+7 x d-cols 8tx..8tx+7
// sK/sV chunk swizzle (c + (row>>3)) & 31 avoids stride-4-row collisions.
// Next tile's K/V are LDG'd into registers before the PV phase (hidden
// behind ~1000 cyc of FFMA2), STS'd at the next loop top.
// smem: sQ 128x132 | sK 64x132 | sV 64x132 | sP 128x68 = 169984 B (1 CTA/SM)
// ---------------------------------------------------------------------------
#define BR 128
#define BC 64
#define ROWP 132
#define PP   68
#define ATTN_SMEM ((BR * ROWP + 2 * BC * ROWP + BR * PP) * 4)

__global__ __launch_bounds__(256, 1)
void flash_attn_kernel(const float* __restrict__ Qg,
                       const float* __restrict__ Kg,
                       const float* __restrict__ Vg,
                       float* __restrict__ Og)
{
    extern __shared__ float smem[];
    float* sQ = smem;                       // BR*ROWP
    float* sK = sQ + BR * ROWP;             // BC*ROWP
    float* sV = sK + BC * ROWP;             // BC*ROWP
    float* sP = sV + BC * ROWP;             // BR*PP

    const int t  = threadIdx.x;
    const int q0 = blockIdx.x * BR;
    const int h  = blockIdx.y;
    const int b  = blockIdx.z;
    const int hk = h >> 2;

    const int ty = t >> 4;                  // 0..15: q rows 8ty..8ty+7
    const int tx = t & 15;                  // k cols 4tx..; d cols 8tx..

    const float scale = 0.08838834764831845f;  // 1/sqrt(128)

    // ---- load Q tile (scaled), unswizzled ----
#pragma unroll
    for (int i = 0; i < 16; i++) {
        int idx = t + i * 256;              // 0..4095 float4 slots
        int row = idx >> 5;                 // 0..127
        int c4  = idx & 31;
        const float4* src = (const float4*)(Qg +
            ((size_t)((b * SEQ + q0 + row) * NHEADS + h)) * HDIM) + c4;
        float4 v = *src;
        v.x *= scale; v.y *= scale; v.z *= scale; v.w *= scale;
        *(float4*)(sQ + row * ROWP + 4 * c4) = v;
    }

    // Per-thread K/V staging slots (8 float4 each tensor):
    //   slot i: row = (t + i*256)>>5, c4 = (t + i*256)&31
    float4 kreg[8], vreg[8];
    {
        const int k0 = 0;
#pragma unroll
        for (int i = 0; i < 8; i++) {
            int idx = t + i * 256;
            int row = idx >> 5;
            int c4  = idx & 31;
            size_t base = ((size_t)((b * SEQ + k0 + row) * NKV + hk)) * HDIM;
            kreg[i] = ((const float4*)(Kg + base))[c4];
            vreg[i] = ((const float4*)(Vg + base))[c4];
        }
    }

    // PV accumulators: acc2[i][dp] = packed dims (8tx+2dp, 8tx+2dp+1), row 8ty+i
    uint64_t acc2[8][4];
#pragma unroll
    for (int i = 0; i < 8; i++)
#pragma unroll
        for (int dp = 0; dp < 4; dp++) acc2[i][dp] = 0ull;
    float row_max[8], row_sum[8];
#pragma unroll
    for (int i = 0; i < 8; i++) { row_max[i] = -INFINITY; row_sum[i] = 0.f; }

    const int NT = SEQ / BC;
    for (int kt = 0; kt < NT; kt++) {
        __syncthreads();   // previous iteration's sK/sV/sP readers done

        // ---- commit staged K/V tile to smem (swizzled chunks) ----
#pragma unroll
        for (int i = 0; i < 8; i++) {
            int idx = t + i * 256;          // 0..2047
            int row = idx >> 5;             // 0..63
            int c4  = idx & 31;
            int sw = 4 * ((c4 + (row >> 3)) & 31);
            *(float4*)(sK + row * ROWP + sw) = kreg[i];
            *(float4*)(sV + row * ROWP + sw) = vreg[i];
        }
        __syncthreads();

        // ---- score phase: s2[qp][j] = packed scores (rows 8ty+2qp, +1) ----
        uint64_t s2[4][4];
#pragma unroll
        for (int qp = 0; qp < 4; qp++)
#pragma unroll
            for (int j = 0; j < 4; j++) s2[qp][j] = 0ull;

        for (int c = 0; c < 32; c++) {      // 32 chunks of 4 dims
            float4 q4[8];
#pragma unroll
            for (int i = 0; i < 8; i++)
                q4[i] = *(const float4*)(sQ + (8 * ty + i) * ROWP + 4 * c);
            float4 k4[4];
#pragma unroll
            for (int j = 0; j < 4; j++) {
                int r = 4 * tx + j;
                k4[j] = *(const float4*)(sK + r * ROWP +
                                         4 * ((c + (r >> 3)) & 31));
            }
            const float* q4f = (const float*)q4;   // [i*4 + d]
            const float* k4f = (const float*)k4;   // [j*4 + d]
#pragma unroll
            for (int d = 0; d < 4; d++) {
                uint64_t q2[4];
#pragma unroll
                for (int qp = 0; qp < 4; qp++)
                    q2[qp] = pack2(q4f[(2 * qp) * 4 + d],
                                   q4f[(2 * qp + 1) * 4 + d]);
#pragma unroll
                for (int j = 0; j < 4; j++) {
                    float kv = k4f[j * 4 + d];
                    uint64_t k2 = pack2(kv, kv);
#pragma unroll
                    for (int qp = 0; qp < 4; qp++)
                        s2[qp][j] = ffma2(q2[qp], k2, s2[qp][j]);
                }
            }
        }

        // unpack scores: s[i][j], i = row 8ty+i, j = col 4tx+j
        float s[8][4];
#pragma unroll
        for (int qp = 0; qp < 4; qp++)
#pragma unroll
            for (int j = 0; j < 4; j++) {
                float2 u = unpack2(s2[qp][j]);
                s[2 * qp][j]     = u.x;
                s[2 * qp + 1][j] = u.y;
            }

        // ---- streaming softmax (row reductions over 16-lane tx groups) ----
#pragma unroll
        for (int i = 0; i < 8; i++) {
            float tm = fmaxf(fmaxf(s[i][0], s[i][1]), fmaxf(s[i][2], s[i][3]));
            tm = fmaxf(tm, __shfl_xor_sync(0xffffffffu, tm, 1, 16));
            tm = fmaxf(tm, __shfl_xor_sync(0xffffffffu, tm, 2, 16));
            tm = fmaxf(tm, __shfl_xor_sync(0xffffffffu, tm, 4, 16));
            tm = fmaxf(tm, __shfl_xor_sync(0xffffffffu, tm, 8, 16));
            float mn = fmaxf(row_max[i], tm);
            float al = __expf(row_max[i] - mn);   // 0 on first tile
            float ls = 0.f;
#pragma unroll
            for (int j = 0; j < 4; j++) {
                s[i][j] = __expf(s[i][j] - mn);
                ls += s[i][j];
            }
            ls += __shfl_xor_sync(0xffffffffu, ls, 1, 16);
            ls += __shfl_xor_sync(0xffffffffu, ls, 2, 16);
            ls += __shfl_xor_sync(0xffffffffu, ls, 4, 16);
            ls += __shfl_xor_sync(0xffffffffu, ls, 8, 16);
            row_sum[i] = row_sum[i] * al + ls;
            row_max[i] = mn;
            uint64_t al2 = pack2(al, al);
#pragma unroll
            for (int dp = 0; dp < 4; dp++)
                acc2[i][dp] = fmul2(acc2[i][dp], al2);
        }

        // ---- store P rows (pitch 68, STS.128) ----
#pragma unroll
        for (int i = 0; i < 8; i++) {
            float4 pv = make_float4(s[i][0], s[i][1], s[i][2], s[i][3]);
            *(float4*)(sP + (8 * ty + i) * PP + 4 * tx) = pv;
        }
        __syncthreads();

        // ---- prefetch next tile's K/V into registers (hidden by PV) ----
        if (kt + 1 < NT) {
            const int kn = (kt + 1) * BC;
#pragma unroll
            for (int i = 0; i < 8; i++) {
                int idx = t + i * 256;
                int row = idx >> 5;
                int c4  = idx & 31;
                size_t base =
                    ((size_t)((b * SEQ + kn + row) * NKV + hk)) * HDIM;
                kreg[i] = ((const float4*)(Kg + base))[c4];
                vreg[i] = ((const float4*)(Vg + base))[c4];
            }
        }

        // ---- PV: acc[8ty+i][8tx..] += P[8ty+i][j] * V[j][8tx..] ----
#pragma unroll 4
        for (int j = 0; j < BC; j++) {
            float p[8];
#pragma unroll
            for (int i = 0; i < 8; i++)
                p[i] = sP[(8 * ty + i) * PP + j];   // broadcast scalar LDS
            int rot = j >> 3;
            float4 va = *(const float4*)(sV + j * ROWP +
                                         4 * ((2 * tx + rot) & 31));
            float4 vb = *(const float4*)(sV + j * ROWP +
                                         4 * ((2 * tx + 1 + rot) & 31));
            uint64_t v2[4] = { pack2(va.x, va.y), pack2(va.z, va.w),
                               pack2(vb.x, vb.y), pack2(vb.z, vb.w) };
#pragma unroll
            for (int i = 0; i < 8; i++) {
                uint64_t p2 = pack2(p[i], p[i]);
#pragma unroll
                for (int dp = 0; dp < 4; dp++)
                    acc2[i][dp] = ffma2(p2, v2[dp], acc2[i][dp]);
            }
        }
    }

    // ---- normalize + store: rows 8ty+i, dims 8tx..8tx+7 ----
#pragma unroll
    for (int i = 0; i < 8; i++) {
        float inv = 1.0f / row_sum[i];
        uint64_t inv2 = pack2(inv, inv);
        float* orow = Og + ((size_t)((b * SEQ + q0 + 8 * ty + i) * NHEADS + h))
                          * HDIM + 8 * tx;
        float2 u0 = unpack2(fmul2(acc2[i][0], inv2));
        float2 u1 = unpack2(fmul2(acc2[i][1], inv2));
        float2 u2 = unpack2(fmul2(acc2[i][2], inv2));
        float2 u3 = unpack2(fmul2(acc2[i][3], inv2));
        *(float4*)(orow)     = make_float4(u0.x, u0.y, u1.x, u1.y);
        *(float4*)(orow + 4) = make_float4(u2.x, u2.y, u3.x, u3.y);
    }
}

// ---------------------------------------------------------------------------
// Launch
// ---------------------------------------------------------------------------
extern "C" void kernel_launch(void* const* d_in, const int* in_sizes, int n_in,
                              void* d_out, int out_size)
{
    const float* x  = (const float*)d_in[0];
    const float* wq = (const float*)d_in[1];
    const float* bq = (const float*)d_in[2];
    const float* wk = (const float*)d_in[3];
    const float* bk = (const float*)d_in[4];
    const float* wv = (const float*)d_in[5];
    const float* bv = (const float*)d_in[6];
    const float* wo = (const float*)d_in[7];
    const float* bo = (const float*)d_in[8];
    float* out = (float*)d_out;

    float *Q, *K, *V, *O;
    cudaGetSymbolAddress((void**)&Q, g_Q);
    cudaGetSymbolAddress((void**)&K, g_K);
    cudaGetSymbolAddress((void**)&V, g_V);
    cudaGetSymbolAddress((void**)&O, g_O);

    // QKV projections
    sgemm_bias_kernel<<<dim3(QDIM / 128, MTOT / 128), 256>>>(
        x, wq, bq, Q, MTOT, QDIM, DMODEL);
    sgemm_bias_kernel<<<dim3(KVDIM / 128, MTOT / 128), 256>>>(
        x, wk, bk, K, MTOT, KVDIM, DMODEL);
    sgemm_bias_kernel<<<dim3(KVDIM / 128, MTOT / 128), 256>>>(
        x, wv, bv, V, MTOT, KVDIM, DMODEL);

    // Attention
    cudaFuncSetAttribute(flash_attn_kernel,
                         cudaFuncAttributeMaxDynamicSharedMemorySize, ATTN_SMEM);
    flash_attn_kernel<<<dim3(SEQ / BR, NHEADS, BATCH), 256, ATTN_SMEM>>>(
        Q, K, V, O);

    // Output projection
    sgemm_bias_kernel<<<dim3(DMODEL / 128, MTOT / 128), 256>>>(
        O, wo, bo, out, MTOT, DMODEL, DMODEL);
}